// round 2
// baseline (speedup 1.0000x reference)
#include <cuda_runtime.h>
#include <math.h>

// ---------------------------------------------------------------------------
// FFNerf fused inference, fp32 baseline.
// Layers:
//   x_emb = posenc(pos, L=10) -> 63     d_emb = posenc(dirs, L=4) -> 27
//   b1: 63->128, 4x 128->128 (relu)
//   b2: [h|x_emb](191)->128, 128->128, 128->128 (relu), 128->129 (linear)
//       sigma = relu(col 128), feat = cols 0..127
//   b3: [feat|d_emb](155)->64 (relu), 64->3 -> sigmoid = color
// Output buffer layout assumed: color row-major (3*N floats) then sigma (N).
// ---------------------------------------------------------------------------

constexpr int TILE     = 64;    // points per CTA
constexpr int NTHREADS = 256;   // (m = tid & 63, ng = tid >> 6)
constexpr int AP   = 129;       // activation pitch (odd -> conflict-free)
constexpr int XP   = 65;        // x_emb pitch
constexpr int DPCH = 33;        // d_emb pitch
constexpr int WCHUNK = 32;      // weight rows staged per chunk

// smem layout (floats)
constexpr int OFF_XE = 0;
constexpr int OFF_DE = OFF_XE + TILE * XP;     // 4160
constexpr int OFF_A  = OFF_DE + TILE * DPCH;   // +2112
constexpr int OFF_B  = OFF_A  + TILE * AP;     // +8256
constexpr int OFF_WS = OFF_B  + TILE * AP;     // +8256
constexpr int SMEM_FLOATS = OFF_WS + WCHUNK * AP;  // + 4128 = 26912
constexpr int SMEM_BYTES  = SMEM_FLOATS * 4;       // 107648 B -> 2 CTAs/SM

// Accumulate one K-phase of a layer: acc[c] += sum_k act[m][k] * W[k][ncol0+c]
// Weights staged through smem in WCHUNK-row slabs (contiguous global copy).
// VEC4: float4 broadcast reads of the weight row (requires Nout%4==0, NC%4==0,
// ncol0%4==0 — true for all call sites).
template <int NC, bool VEC4>
__device__ __forceinline__ void gemm_phase(
    float* acc, const float* __restrict__ Wg, int K, int Nout,
    const float* __restrict__ act, int pitch,
    float* Ws, int m, int ncol0, int tid)
{
    for (int k0 = 0; k0 < K; k0 += WCHUNK) {
        int rows  = min(WCHUNK, K - k0);
        int elems = rows * Nout;
        const float* src = Wg + k0 * Nout;   // contiguous slab
        for (int i = tid; i < elems; i += NTHREADS) Ws[i] = src[i];
        __syncthreads();
        #pragma unroll 4
        for (int kk = 0; kk < rows; ++kk) {
            float a = act[m * pitch + k0 + kk];
            const float* wrow = Ws + kk * Nout + ncol0;
            if (VEC4) {
                const float4* w4 = reinterpret_cast<const float4*>(wrow);
                #pragma unroll
                for (int c = 0; c < NC / 4; ++c) {
                    float4 w = w4[c];
                    acc[4*c+0] += a * w.x;
                    acc[4*c+1] += a * w.y;
                    acc[4*c+2] += a * w.z;
                    acc[4*c+3] += a * w.w;
                }
            } else {
                #pragma unroll
                for (int c = 0; c < NC; ++c) acc[c] += a * wrow[c];
            }
        }
        __syncthreads();
    }
}

// Full layer: optional second concat phase (actB), relu, store to `out` (pitch AP).
template <int NC, bool RELU>
__device__ __forceinline__ void layer(
    const float* __restrict__ W, int Nout,
    const float* __restrict__ actA, int pA, int KA,
    const float* __restrict__ actB, int pB, int KB,
    float* out, float* Ws, int m, int ng, int tid)
{
    float acc[NC];
    #pragma unroll
    for (int c = 0; c < NC; ++c) acc[c] = 0.f;
    int ncol0 = ng * NC;
    gemm_phase<NC, true>(acc, W, KA, Nout, actA, pA, Ws, m, ncol0, tid);
    if (actB)
        gemm_phase<NC, true>(acc, W + KA * Nout, KB, Nout, actB, pB, Ws, m, ncol0, tid);
    #pragma unroll
    for (int c = 0; c < NC; ++c) {
        float v = acc[c];
        if (RELU) v = fmaxf(v, 0.f);
        out[m * AP + ncol0 + c] = v;
    }
    __syncthreads();
}

// b2_w3: K=128 -> Nout=129. feat = cols 0..127 (linear, to smem),
// sigma = relu(col 128) written straight to global.
__device__ __forceinline__ void layer_b2w3(
    const float* __restrict__ W, const float* __restrict__ act,
    float* outFeat, float* __restrict__ sigma_out, int g0,
    float* Ws, int m, int ng, int tid)
{
    const int Nout = 129;
    const int K = 128;
    float acc[32];
    #pragma unroll
    for (int c = 0; c < 32; ++c) acc[c] = 0.f;
    float ssum = 0.f;
    int ncol0 = ng * 32;
    for (int k0 = 0; k0 < K; k0 += WCHUNK) {
        int rows  = WCHUNK;
        int elems = rows * Nout;
        const float* src = W + k0 * Nout;
        for (int i = tid; i < elems; i += NTHREADS) Ws[i] = src[i];
        __syncthreads();
        #pragma unroll 4
        for (int kk = 0; kk < rows; ++kk) {
            float a = act[m * AP + k0 + kk];
            const float* wrow = Ws + kk * Nout;
            #pragma unroll
            for (int c = 0; c < 32; ++c) acc[c] += a * wrow[ncol0 + c];
            ssum += a * wrow[128];
        }
        __syncthreads();
    }
    #pragma unroll
    for (int c = 0; c < 32; ++c)
        outFeat[m * AP + ncol0 + c] = acc[c];      // linear (no relu)
    if (ng == 0)
        sigma_out[g0 + m] = fmaxf(ssum, 0.f);
    __syncthreads();
}

__global__ void __launch_bounds__(NTHREADS)
ffnerf_fused_kernel(
    const float* __restrict__ pos,  const float* __restrict__ dirs,
    const float* __restrict__ w10,  const float* __restrict__ w11,
    const float* __restrict__ w12,  const float* __restrict__ w13,
    const float* __restrict__ w14,
    const float* __restrict__ w20,  const float* __restrict__ w21,
    const float* __restrict__ w22,  const float* __restrict__ w23,
    const float* __restrict__ w30,  const float* __restrict__ w31,
    float* __restrict__ out, int npts)
{
    extern __shared__ float smem[];
    float* XE = smem + OFF_XE;
    float* DE = smem + OFF_DE;
    float* A  = smem + OFF_A;
    float* B  = smem + OFF_B;
    float* Ws = smem + OFF_WS;

    const int tid = threadIdx.x;
    const int m   = tid & (TILE - 1);
    const int ng  = tid >> 6;
    const int g0  = blockIdx.x * TILE;

    // --- positional encodings -------------------------------------------
    if (tid < TILE) {
        int g = g0 + tid;
        float p[3] = { pos[g*3+0], pos[g*3+1], pos[g*3+2] };
        float* xe = XE + tid * XP;
        xe[0] = p[0]; xe[1] = p[1]; xe[2] = p[2];
        #pragma unroll
        for (int j = 0; j < 10; ++j) {
            float f = (float)(1 << j);
            #pragma unroll
            for (int c = 0; c < 3; ++c) {
                float sv, cv;
                sincosf(f * p[c], &sv, &cv);
                xe[3 + 6*j + c]     = sv;
                xe[3 + 6*j + 3 + c] = cv;
            }
        }
    } else if (tid < 2 * TILE) {
        int mm = tid - TILE;
        int g = g0 + mm;
        float d[3] = { dirs[g*3+0], dirs[g*3+1], dirs[g*3+2] };
        float* de = DE + mm * DPCH;
        de[0] = d[0]; de[1] = d[1]; de[2] = d[2];
        #pragma unroll
        for (int j = 0; j < 4; ++j) {
            float f = (float)(1 << j);
            #pragma unroll
            for (int c = 0; c < 3; ++c) {
                float sv, cv;
                sincosf(f * d[c], &sv, &cv);
                de[3 + 6*j + c]     = sv;
                de[3 + 6*j + 3 + c] = cv;
            }
        }
    }
    __syncthreads();

    // --- block 1 ---------------------------------------------------------
    layer<32, true>(w10, 128, XE, XP, 63,  nullptr, 0, 0,  A, Ws, m, ng, tid);
    layer<32, true>(w11, 128, A,  AP, 128, nullptr, 0, 0,  B, Ws, m, ng, tid);
    layer<32, true>(w12, 128, B,  AP, 128, nullptr, 0, 0,  A, Ws, m, ng, tid);
    layer<32, true>(w13, 128, A,  AP, 128, nullptr, 0, 0,  B, Ws, m, ng, tid);
    layer<32, true>(w14, 128, B,  AP, 128, nullptr, 0, 0,  A, Ws, m, ng, tid);

    // --- block 2 (concat [h | x_emb]) ------------------------------------
    layer<32, true>(w20, 128, A,  AP, 128, XE, XP, 63,     B, Ws, m, ng, tid);
    layer<32, true>(w21, 128, B,  AP, 128, nullptr, 0, 0,  A, Ws, m, ng, tid);
    layer<32, true>(w22, 128, A,  AP, 128, nullptr, 0, 0,  B, Ws, m, ng, tid);
    // 128 -> 129: feat into A, sigma to global
    layer_b2w3(w23, B, A, out + (size_t)3 * npts, g0, Ws, m, ng, tid);

    // --- block 3 (concat [feat | d_emb]) ----------------------------------
    layer<16, true>(w30, 64, A, AP, 128, DE, DPCH, 27,     B, Ws, m, ng, tid);

    // 64 -> 3, sigmoid -> color
    if (tid < TILE) {
        const float* act = B + tid * AP;
        float c0 = 0.f, c1 = 0.f, c2 = 0.f;
        #pragma unroll 8
        for (int k = 0; k < 64; ++k) {
            float a = act[k];
            c0 += a * __ldg(w31 + k*3 + 0);
            c1 += a * __ldg(w31 + k*3 + 1);
            c2 += a * __ldg(w31 + k*3 + 2);
        }
        int g = g0 + tid;
        out[g*3 + 0] = 1.f / (1.f + expf(-c0));
        out[g*3 + 1] = 1.f / (1.f + expf(-c1));
        out[g*3 + 2] = 1.f / (1.f + expf(-c2));
    }
}

extern "C" void kernel_launch(void* const* d_in, const int* in_sizes, int n_in,
                              void* d_out, int out_size)
{
    const float* pos  = (const float*)d_in[0];
    const float* dirs = (const float*)d_in[1];
    const float* w10  = (const float*)d_in[2];
    const float* w11  = (const float*)d_in[3];
    const float* w12  = (const float*)d_in[4];
    const float* w13  = (const float*)d_in[5];
    const float* w14  = (const float*)d_in[6];
    const float* w20  = (const float*)d_in[7];
    const float* w21  = (const float*)d_in[8];
    const float* w22  = (const float*)d_in[9];
    const float* w23  = (const float*)d_in[10];
    const float* w30  = (const float*)d_in[11];
    const float* w31  = (const float*)d_in[12];

    int npts = in_sizes[0] / 3;
    int nblocks = (npts + TILE - 1) / TILE;

    cudaFuncSetAttribute(ffnerf_fused_kernel,
                         cudaFuncAttributeMaxDynamicSharedMemorySize, SMEM_BYTES);

    ffnerf_fused_kernel<<<nblocks, NTHREADS, SMEM_BYTES>>>(
        pos, dirs, w10, w11, w12, w13, w14,
        w20, w21, w22, w23, w30, w31,
        (float*)d_out, npts);
    (void)n_in; (void)out_size;
}

// round 3
// speedup vs baseline: 1.0945x; 1.0945x over previous
#include <cuda_runtime.h>
#include <math.h>

// ---------------------------------------------------------------------------
// FFNerf fused inference, fp32, register-tiled (2 pts/thread), direct-LDG
// weights (warp-uniform broadcast, L1/L2 resident), transposed activations.
//
//   x_emb = posenc(pos, L=10) -> 63     d_emb = posenc(dirs, L=4) -> 27
//   b1: 63->128, 4x 128->128 (relu)
//   b2: [h|x_emb](191)->128, 128->128, 128->128 (relu), 128->129 (linear)
//       sigma = relu(col 128), feat = cols 0..127
//   b3: [feat|d_emb](155)->64 (relu), 64->3 -> sigmoid = color
// Output: color row-major (3*N) then sigma (N).
//
// Activations live in smem TRANSPOSED: X[col][pt], pitch PM. Thread layout:
// lane pg = tid&31 owns points {2pg, 2pg+1}; warp cg = tid>>5 owns a column
// slice. Weight reads are warp-uniform LDG.128 -> broadcast, cache-served.
// ---------------------------------------------------------------------------

constexpr int TILE     = 64;     // points per CTA
constexpr int NTHREADS = 256;    // 8 warps
constexpr int PM       = 64;     // point-dim pitch of transposed activations

// smem layout (floats): XE 64 rows, DE 28 rows, A/B 128 rows, all pitch PM
constexpr int ROWS_XE = 64;      // 63 used
constexpr int ROWS_DE = 28;      // 27 used
constexpr int SMEM_FLOATS = (ROWS_XE + ROWS_DE + 128 + 128) * PM;  // 22272
constexpr int SMEM_BYTES  = SMEM_FLOATS * 4;                        // 89088

// padded copy of b2_w3 (128 x 129 -> pitch 132, 16B-aligned rows)
__device__ __align__(16) float g_w23pad[128 * 132];

__global__ void pad_w23_kernel(const float* __restrict__ w23) {
    int i = blockIdx.x * blockDim.x + threadIdx.x;
    if (i < 128 * 129) {
        int r = i / 129;
        int c = i - r * 129;
        g_w23pad[r * 132 + c] = w23[i];
    }
}

// acc[i][c] += act[k][2pg+i] * W[k][ncol0+c], K iterations.
// Wg points at the weight matrix base (row-major K x Nout); sigma taps col 128.
template <int NC, bool SIGMA>
__device__ __forceinline__ void mac_phase(
    float (&acc)[2][NC], float& ss0, float& ss1,
    const float* __restrict__ Wg, int Nout, int K,
    const float* __restrict__ act,   // smem, transposed, pitch PM
    int ncol0, int pg, bool sig)
{
    const float* __restrict__ wp = Wg + ncol0;
    const float* __restrict__ ap = act + 2 * pg;
    #pragma unroll 4
    for (int k = 0; k < K; ++k) {
        float2 a = *reinterpret_cast<const float2*>(ap + k * PM);
        const float4* w4 = reinterpret_cast<const float4*>(wp + k * Nout);
        #pragma unroll
        for (int j = 0; j < NC / 4; ++j) {
            float4 w = w4[j];
            acc[0][4*j+0] = fmaf(a.x, w.x, acc[0][4*j+0]);
            acc[0][4*j+1] = fmaf(a.x, w.y, acc[0][4*j+1]);
            acc[0][4*j+2] = fmaf(a.x, w.z, acc[0][4*j+2]);
            acc[0][4*j+3] = fmaf(a.x, w.w, acc[0][4*j+3]);
            acc[1][4*j+0] = fmaf(a.y, w.x, acc[1][4*j+0]);
            acc[1][4*j+1] = fmaf(a.y, w.y, acc[1][4*j+1]);
            acc[1][4*j+2] = fmaf(a.y, w.z, acc[1][4*j+2]);
            acc[1][4*j+3] = fmaf(a.y, w.w, acc[1][4*j+3]);
        }
        if (SIGMA) {
            if (sig) {
                float wv = __ldg(Wg + k * Nout + 128);
                ss0 = fmaf(a.x, wv, ss0);
                ss1 = fmaf(a.y, wv, ss1);
            }
        }
    }
}

// One layer: optional concat second phase, relu, transposed store, barrier.
template <int NC, bool RELU, bool SIGMA>
__device__ __forceinline__ void run_layer(
    const float* __restrict__ Wg, int Nout,
    const float* __restrict__ actA, int KA,
    const float* __restrict__ actB, int KB,
    float* __restrict__ Xout,
    float* __restrict__ sigma_out, int g0,
    int pg, int cg)
{
    float acc[2][NC];
    #pragma unroll
    for (int i = 0; i < 2; ++i)
        #pragma unroll
        for (int c = 0; c < NC; ++c) acc[i][c] = 0.f;
    float ss0 = 0.f, ss1 = 0.f;
    const int ncol0 = cg * NC;
    const bool sig = SIGMA && (cg == 7);

    mac_phase<NC, SIGMA>(acc, ss0, ss1, Wg, Nout, KA, actA, ncol0, pg, sig);
    if (actB)
        mac_phase<NC, false>(acc, ss0, ss1, Wg + KA * Nout, Nout, KB, actB,
                             ncol0, pg, false);

    #pragma unroll
    for (int c = 0; c < NC; ++c) {
        float v0 = acc[0][c], v1 = acc[1][c];
        if (RELU) { v0 = fmaxf(v0, 0.f); v1 = fmaxf(v1, 0.f); }
        *reinterpret_cast<float2*>(&Xout[(ncol0 + c) * PM + 2 * pg]) =
            make_float2(v0, v1);
    }
    if (SIGMA && sig) {
        sigma_out[g0 + 2 * pg + 0] = fmaxf(ss0, 0.f);
        sigma_out[g0 + 2 * pg + 1] = fmaxf(ss1, 0.f);
    }
    __syncthreads();
}

__global__ void __launch_bounds__(NTHREADS, 2)
ffnerf_fused_kernel(
    const float* __restrict__ pos,  const float* __restrict__ dirs,
    const float* __restrict__ w10,  const float* __restrict__ w11,
    const float* __restrict__ w12,  const float* __restrict__ w13,
    const float* __restrict__ w14,
    const float* __restrict__ w20,  const float* __restrict__ w21,
    const float* __restrict__ w22,
    const float* __restrict__ w30,  const float* __restrict__ w31,
    float* __restrict__ out, int npts)
{
    extern __shared__ float smem[];
    float* XE = smem;                                  // [63][PM]
    float* DE = smem + ROWS_XE * PM;                   // [27][PM]
    float* A  = smem + (ROWS_XE + ROWS_DE) * PM;       // [128][PM]
    float* B  = A + 128 * PM;                          // [128][PM]

    const int tid = threadIdx.x;
    const int pg  = tid & 31;
    const int cg  = tid >> 5;
    const int g0  = blockIdx.x * TILE;

    // --- positional encodings (transposed: feat-major) --------------------
    if (tid < TILE) {
        int g = g0 + tid;
        float p[3] = { pos[g*3+0], pos[g*3+1], pos[g*3+2] };
        XE[0*PM + tid] = p[0];
        XE[1*PM + tid] = p[1];
        XE[2*PM + tid] = p[2];
        #pragma unroll
        for (int j = 0; j < 10; ++j) {
            float f = (float)(1 << j);
            #pragma unroll
            for (int c = 0; c < 3; ++c) {
                float sv, cv;
                sincosf(f * p[c], &sv, &cv);
                XE[(3 + 6*j + c)     * PM + tid] = sv;
                XE[(3 + 6*j + 3 + c) * PM + tid] = cv;
            }
        }
    } else if (tid < 2 * TILE) {
        int m = tid - TILE;
        int g = g0 + m;
        float d[3] = { dirs[g*3+0], dirs[g*3+1], dirs[g*3+2] };
        DE[0*PM + m] = d[0];
        DE[1*PM + m] = d[1];
        DE[2*PM + m] = d[2];
        #pragma unroll
        for (int j = 0; j < 4; ++j) {
            float f = (float)(1 << j);
            #pragma unroll
            for (int c = 0; c < 3; ++c) {
                float sv, cv;
                sincosf(f * d[c], &sv, &cv);
                DE[(3 + 6*j + c)     * PM + m] = sv;
                DE[(3 + 6*j + 3 + c) * PM + m] = cv;
            }
        }
    }
    __syncthreads();

    float* sigma_out = out + (size_t)3 * npts;

    // --- block 1 ----------------------------------------------------------
    run_layer<16, true, false>(w10, 128, XE, 63,  nullptr, 0, A, nullptr, g0, pg, cg);
    run_layer<16, true, false>(w11, 128, A, 128,  nullptr, 0, B, nullptr, g0, pg, cg);
    run_layer<16, true, false>(w12, 128, B, 128,  nullptr, 0, A, nullptr, g0, pg, cg);
    run_layer<16, true, false>(w13, 128, A, 128,  nullptr, 0, B, nullptr, g0, pg, cg);
    run_layer<16, true, false>(w14, 128, B, 128,  nullptr, 0, A, nullptr, g0, pg, cg);

    // --- block 2 (concat [h | x_emb]) -------------------------------------
    run_layer<16, true, false>(w20, 128, A, 128,  XE, 63,     B, nullptr, g0, pg, cg);
    run_layer<16, true, false>(w21, 128, B, 128,  nullptr, 0, A, nullptr, g0, pg, cg);
    run_layer<16, true, false>(w22, 128, A, 128,  nullptr, 0, B, nullptr, g0, pg, cg);
    // b2_w3 via padded copy (pitch 132): feat -> A (linear), sigma -> global
    run_layer<16, false, true>(g_w23pad, 132, B, 128, nullptr, 0, A,
                               sigma_out, g0, pg, cg);

    // --- block 3 (concat [feat | d_emb]) -----------------------------------
    run_layer<8, true, false>(w30, 64, A, 128,  DE, 27,      B, nullptr, g0, pg, cg);

    // --- 64 -> 3, sigmoid -> color ----------------------------------------
    if (tid < TILE) {
        int m = tid;
        float c0 = 0.f, c1 = 0.f, c2 = 0.f;
        #pragma unroll 8
        for (int k = 0; k < 64; ++k) {
            float a = B[k * PM + m];
            c0 = fmaf(a, __ldg(w31 + k*3 + 0), c0);
            c1 = fmaf(a, __ldg(w31 + k*3 + 1), c1);
            c2 = fmaf(a, __ldg(w31 + k*3 + 2), c2);
        }
        int g = g0 + m;
        out[g*3 + 0] = 1.f / (1.f + expf(-c0));
        out[g*3 + 1] = 1.f / (1.f + expf(-c1));
        out[g*3 + 2] = 1.f / (1.f + expf(-c2));
    }
}

extern "C" void kernel_launch(void* const* d_in, const int* in_sizes, int n_in,
                              void* d_out, int out_size)
{
    const float* pos  = (const float*)d_in[0];
    const float* dirs = (const float*)d_in[1];
    const float* w10  = (const float*)d_in[2];
    const float* w11  = (const float*)d_in[3];
    const float* w12  = (const float*)d_in[4];
    const float* w13  = (const float*)d_in[5];
    const float* w14  = (const float*)d_in[6];
    const float* w20  = (const float*)d_in[7];
    const float* w21  = (const float*)d_in[8];
    const float* w22  = (const float*)d_in[9];
    const float* w23  = (const float*)d_in[10];
    const float* w30  = (const float*)d_in[11];
    const float* w31  = (const float*)d_in[12];

    int npts = in_sizes[0] / 3;
    int nblocks = npts / TILE;

    cudaFuncSetAttribute(ffnerf_fused_kernel,
                         cudaFuncAttributeMaxDynamicSharedMemorySize, SMEM_BYTES);

    pad_w23_kernel<<<(128 * 129 + 255) / 256, 256>>>(w23);
    ffnerf_fused_kernel<<<nblocks, NTHREADS, SMEM_BYTES>>>(
        pos, dirs, w10, w11, w12, w13, w14,
        w20, w21, w22, w30, w31,
        (float*)d_out, npts);
    (void)n_in; (void)out_size;
}

// round 4
// speedup vs baseline: 1.1811x; 1.0792x over previous
#include <cuda_runtime.h>
#include <math.h>
#include <stdint.h>

// ---------------------------------------------------------------------------
// FFNerf fused inference via mma.sync tf32 (3xTF32 split precision).
//
// Per CTA: 64 points. 8 warps = 4 (M) x 2 (N). Each warp: 16 x (Nout/2) tile.
// Activations: fp32 in smem, row-major [pt][k] (pitch ≡ 4 mod 32 -> LDS
// conflict-free for A-fragments). Split hi/lo at register load.
// Weights: pre-split tf32 hi/lo into padded __device__ scratch; B-fragments
// read by LDG (L1/L2 resident, shared across M-warps and CTAs).
//   x·w ≈ lo·hi + hi·lo + hi·hi   (3 mma, ~22-bit effective mantissa)
//
// Network:
//   x_emb=posenc(pos,10)->63 (pad 64)   d_emb=posenc(dirs,4)->27 (pad 32)
//   b1: 63->128, 4x 128->128 relu
//   b2: [h|x]191(pad 192)->128, 128->128, 128->128 relu, 128->129 linear
//       sigma=relu(col128) [scalar fp32 path], feat=cols 0..127
//   b3: [feat|d]155(pad 160)->64 relu, 64->3 sigmoid
// Output: color (3N) then sigma (N).
// ---------------------------------------------------------------------------

constexpr int TILE     = 64;
constexpr int NTHREADS = 256;

// smem act buffers (fp32), pitches ≡ 4 (mod 32)
constexpr int XP = 68;    // x_emb [64][68], k=0..63 (63 real + 1 zero)
constexpr int DP = 36;    // d_emb [64][36], k=0..31 (27 real + 5 zero)
constexpr int HP = 132;   // hidden [64][132]
constexpr int OFF_X  = 0;
constexpr int OFF_D  = OFF_X + 64 * XP;        // 4352
constexpr int OFF_H0 = OFF_D + 64 * DP;        // 6656
constexpr int OFF_H1 = OFF_H0 + 64 * HP;       // 15104
constexpr int SMEM_FLOATS = OFF_H1 + 64 * HP;  // 23552
constexpr int SMEM_BYTES  = SMEM_FLOATS * 4;   // 94208 -> 2 CTAs/SM

// padded split-weight scratch offsets (floats)
constexpr int O10 = 0;                  // [ 64][128]
constexpr int O11 = O10 + 64 * 128;     // [128][128]
constexpr int O12 = O11 + 128 * 128;
constexpr int O13 = O12 + 128 * 128;
constexpr int O14 = O13 + 128 * 128;
constexpr int O20 = O14 + 128 * 128;    // [192][128]
constexpr int O21 = O20 + 192 * 128;
constexpr int O22 = O21 + 128 * 128;
constexpr int O23 = O22 + 128 * 128;    // [128][128] (col 128 excluded)
constexpr int O30 = O23 + 128 * 128;    // [160][ 64]
constexpr int WTOTAL = O30 + 160 * 64;  // 157696

__device__ float g_wh[WTOTAL];
__device__ float g_wl[WTOTAL];

__device__ __forceinline__ uint32_t tf32_rna(float x) {
    uint32_t r;
    asm("cvt.rna.tf32.f32 %0, %1;" : "=r"(r) : "f"(x));
    return r;
}

// Split padded weight into tf32 hi/lo scratch.
__global__ void prep_split_kernel(const float* __restrict__ src,
                                  int srcRows, int srcCols, int srcPitch,
                                  int dstOff, int dstRows, int dstCols)
{
    int i = blockIdx.x * blockDim.x + threadIdx.x;
    if (i >= dstRows * dstCols) return;
    int r = i / dstCols, c = i - r * dstCols;
    float v = (r < srcRows && c < srcCols) ? src[r * srcPitch + c] : 0.f;
    uint32_t h = tf32_rna(v);
    float hf = __uint_as_float(h);
    uint32_t l = tf32_rna(v - hf);
    g_wh[dstOff + i] = hf;
    g_wl[dstOff + i] = __uint_as_float(l);
}

__device__ __forceinline__ void mma_tf32(float* c, const uint32_t* a,
                                         uint32_t b0, uint32_t b1) {
    asm volatile(
        "mma.sync.aligned.m16n8k8.row.col.f32.tf32.tf32.f32 "
        "{%0,%1,%2,%3}, {%4,%5,%6,%7}, {%8,%9}, {%0,%1,%2,%3};"
        : "+f"(c[0]), "+f"(c[1]), "+f"(c[2]), "+f"(c[3])
        : "r"(a[0]), "r"(a[1]), "r"(a[2]), "r"(a[3]), "r"(b0), "r"(b1));
}

// One K-phase over NT n-tiles. act: fp32 smem [pt][k]; W: split scratch.
template <int NT>
__device__ __forceinline__ void mma_phase(
    float (&c)[NT][4],
    const float* __restrict__ act, int pitch, int K,
    const float* __restrict__ Wh, const float* __restrict__ Wl, int Nout,
    int m0, int n0, int g, int t)
{
    const float* ar0 = act + (m0 + g) * pitch + t;
    const float* ar1 = act + (m0 + g + 8) * pitch + t;
    for (int k0 = 0; k0 < K; k0 += 8) {
        float a0 = ar0[k0], a1 = ar1[k0], a2 = ar0[k0 + 4], a3 = ar1[k0 + 4];
        uint32_t ah[4], al[4];
        ah[0] = tf32_rna(a0); al[0] = tf32_rna(a0 - __uint_as_float(ah[0]));
        ah[1] = tf32_rna(a1); al[1] = tf32_rna(a1 - __uint_as_float(ah[1]));
        ah[2] = tf32_rna(a2); al[2] = tf32_rna(a2 - __uint_as_float(ah[2]));
        ah[3] = tf32_rna(a3); al[3] = tf32_rna(a3 - __uint_as_float(ah[3]));
        const float* bh = Wh + (k0 + t) * Nout + n0 + g;
        const float* bl = Wl + (k0 + t) * Nout + n0 + g;
        #pragma unroll
        for (int nt = 0; nt < NT; ++nt) {
            uint32_t bh0 = __float_as_uint(__ldg(bh + nt * 8));
            uint32_t bh1 = __float_as_uint(__ldg(bh + 4 * Nout + nt * 8));
            uint32_t bl0 = __float_as_uint(__ldg(bl + nt * 8));
            uint32_t bl1 = __float_as_uint(__ldg(bl + 4 * Nout + nt * 8));
            mma_tf32(c[nt], al, bh0, bh1);   // lo*hi
            mma_tf32(c[nt], ah, bl0, bl1);   // hi*lo
            mma_tf32(c[nt], ah, bh0, bh1);   // hi*hi
        }
    }
}

// Full layer: up to two phases (concat), relu, store fp32 to Hout, barrier.
template <int NT, bool RELU>
__device__ __forceinline__ void run_layer(
    int wOff, int Nout,
    const float* __restrict__ actA, int pA, int KA,
    const float* __restrict__ actB, int pB, int KB,
    float* __restrict__ Hout, int m0, int n0, int g, int t)
{
    float c[NT][4];
    #pragma unroll
    for (int nt = 0; nt < NT; ++nt)
        #pragma unroll
        for (int j = 0; j < 4; ++j) c[nt][j] = 0.f;

    mma_phase<NT>(c, actA, pA, KA, g_wh + wOff, g_wl + wOff, Nout, m0, n0, g, t);
    if (actB)
        mma_phase<NT>(c, actB, pB, KB, g_wh + wOff + KA * Nout,
                      g_wl + wOff + KA * Nout, Nout, m0, n0, g, t);

    #pragma unroll
    for (int nt = 0; nt < NT; ++nt) {
        float v0 = c[nt][0], v1 = c[nt][1], v2 = c[nt][2], v3 = c[nt][3];
        if (RELU) {
            v0 = fmaxf(v0, 0.f); v1 = fmaxf(v1, 0.f);
            v2 = fmaxf(v2, 0.f); v3 = fmaxf(v3, 0.f);
        }
        int col = n0 + nt * 8 + 2 * t;
        *reinterpret_cast<float2*>(&Hout[(m0 + g)     * HP + col]) = make_float2(v0, v1);
        *reinterpret_cast<float2*>(&Hout[(m0 + g + 8) * HP + col]) = make_float2(v2, v3);
    }
    __syncthreads();
}

__global__ void __launch_bounds__(NTHREADS, 2)
ffnerf_mma_kernel(
    const float* __restrict__ pos,  const float* __restrict__ dirs,
    const float* __restrict__ w23,  const float* __restrict__ w31,
    float* __restrict__ out, int npts)
{
    extern __shared__ float smem[];
    float* X  = smem + OFF_X;
    float* D  = smem + OFF_D;
    float* H0 = smem + OFF_H0;
    float* H1 = smem + OFF_H1;

    const int tid    = threadIdx.x;
    const int lane   = tid & 31;
    const int warp   = tid >> 5;
    const int g      = lane >> 2;      // group id 0..7
    const int t      = lane & 3;       // thread-in-group
    const int warp_m = warp & 3;
    const int warp_n = warp >> 2;
    const int m0     = warp_m * 16;
    const int g0     = blockIdx.x * TILE;

    // --- positional encodings (row-major per point) -----------------------
    if (tid < TILE) {
        int gp = g0 + tid;
        float p[3] = { pos[gp*3+0], pos[gp*3+1], pos[gp*3+2] };
        float* xr = X + tid * XP;
        xr[0] = p[0]; xr[1] = p[1]; xr[2] = p[2];
        #pragma unroll
        for (int j = 0; j < 10; ++j) {
            float f = (float)(1 << j);
            #pragma unroll
            for (int cc = 0; cc < 3; ++cc) {
                float sv, cv;
                sincosf(f * p[cc], &sv, &cv);
                xr[3 + 6*j + cc]     = sv;
                xr[3 + 6*j + 3 + cc] = cv;
            }
        }
        xr[63] = 0.f;                      // K pad
    } else if (tid < 2 * TILE) {
        int m = tid - TILE;
        int gp = g0 + m;
        float d[3] = { dirs[gp*3+0], dirs[gp*3+1], dirs[gp*3+2] };
        float* dr = D + m * DP;
        dr[0] = d[0]; dr[1] = d[1]; dr[2] = d[2];
        #pragma unroll
        for (int j = 0; j < 4; ++j) {
            float f = (float)(1 << j);
            #pragma unroll
            for (int cc = 0; cc < 3; ++cc) {
                float sv, cv;
                sincosf(f * d[cc], &sv, &cv);
                dr[3 + 6*j + cc]     = sv;
                dr[3 + 6*j + 3 + cc] = cv;
            }
        }
        #pragma unroll
        for (int z = 27; z < 32; ++z) dr[z] = 0.f;   // K pad
    }
    __syncthreads();

    const int n0_128 = warp_n * 64;   // Nout=128: NT=8
    const int n0_64  = warp_n * 32;   // Nout=64:  NT=4

    // --- block 1 ----------------------------------------------------------
    run_layer<8, true >(O10, 128, X,  XP, 64,  nullptr, 0, 0, H0, m0, n0_128, g, t);
    run_layer<8, true >(O11, 128, H0, HP, 128, nullptr, 0, 0, H1, m0, n0_128, g, t);
    run_layer<8, true >(O12, 128, H1, HP, 128, nullptr, 0, 0, H0, m0, n0_128, g, t);
    run_layer<8, true >(O13, 128, H0, HP, 128, nullptr, 0, 0, H1, m0, n0_128, g, t);
    run_layer<8, true >(O14, 128, H1, HP, 128, nullptr, 0, 0, H0, m0, n0_128, g, t);

    // --- block 2 ----------------------------------------------------------
    run_layer<8, true >(O20, 128, H0, HP, 128, X, XP, 64,     H1, m0, n0_128, g, t);
    run_layer<8, true >(O21, 128, H1, HP, 128, nullptr, 0, 0, H0, m0, n0_128, g, t);
    run_layer<8, true >(O22, 128, H0, HP, 128, nullptr, 0, 0, H1, m0, n0_128, g, t);
    // feat = H1 @ w23[:, :128] (linear) -> H0 ; sigma handled below from H1
    run_layer<8, false>(O23, 128, H1, HP, 128, nullptr, 0, 0, H0, m0, n0_128, g, t);

    // sigma = relu(H1 . w23[:,128])  (exact fp32 scalar path)
    if (tid < TILE) {
        const float* hb = H1 + tid * HP;
        float s = 0.f;
        #pragma unroll 8
        for (int k = 0; k < 128; ++k)
            s = fmaf(hb[k], __ldg(w23 + k * 129 + 128), s);
        out[(size_t)3 * npts + g0 + tid] = fmaxf(s, 0.f);
    }
    __syncthreads();

    // --- block 3 ----------------------------------------------------------
    run_layer<4, true >(O30, 64, H0, HP, 128, D, DP, 32,      H1, m0, n0_64, g, t);

    // 64 -> 3, sigmoid
    if (tid < TILE) {
        const float* act = H1 + tid * HP;
        float c0 = 0.f, c1 = 0.f, c2 = 0.f;
        #pragma unroll 8
        for (int k = 0; k < 64; ++k) {
            float a = act[k];
            c0 = fmaf(a, __ldg(w31 + k*3 + 0), c0);
            c1 = fmaf(a, __ldg(w31 + k*3 + 1), c1);
            c2 = fmaf(a, __ldg(w31 + k*3 + 2), c2);
        }
        int gp = g0 + tid;
        out[gp*3 + 0] = 1.f / (1.f + expf(-c0));
        out[gp*3 + 1] = 1.f / (1.f + expf(-c1));
        out[gp*3 + 2] = 1.f / (1.f + expf(-c2));
    }
}

extern "C" void kernel_launch(void* const* d_in, const int* in_sizes, int n_in,
                              void* d_out, int out_size)
{
    const float* pos  = (const float*)d_in[0];
    const float* dirs = (const float*)d_in[1];
    const float* w10  = (const float*)d_in[2];
    const float* w11  = (const float*)d_in[3];
    const float* w12  = (const float*)d_in[4];
    const float* w13  = (const float*)d_in[5];
    const float* w14  = (const float*)d_in[6];
    const float* w20  = (const float*)d_in[7];
    const float* w21  = (const float*)d_in[8];
    const float* w22  = (const float*)d_in[9];
    const float* w23  = (const float*)d_in[10];
    const float* w30  = (const float*)d_in[11];
    const float* w31  = (const float*)d_in[12];

    int npts = in_sizes[0] / 3;
    int nblocks = npts / TILE;

    auto prep = [](const float* src, int sr, int sc, int sp,
                   int off, int dr, int dc) {
        int n = dr * dc;
        prep_split_kernel<<<(n + 255) / 256, 256>>>(src, sr, sc, sp, off, dr, dc);
    };
    prep(w10,  63, 128, 128, O10,  64, 128);
    prep(w11, 128, 128, 128, O11, 128, 128);
    prep(w12, 128, 128, 128, O12, 128, 128);
    prep(w13, 128, 128, 128, O13, 128, 128);
    prep(w14, 128, 128, 128, O14, 128, 128);
    prep(w20, 191, 128, 128, O20, 192, 128);
    prep(w21, 128, 128, 128, O21, 128, 128);
    prep(w22, 128, 128, 128, O22, 128, 128);
    prep(w23, 128, 128, 129, O23, 128, 128);   // exclude sigma col
    prep(w30, 155,  64,  64, O30, 160,  64);

    cudaFuncSetAttribute(ffnerf_mma_kernel,
                         cudaFuncAttributeMaxDynamicSharedMemorySize, SMEM_BYTES);
    ffnerf_mma_kernel<<<nblocks, NTHREADS, SMEM_BYTES>>>(
        pos, dirs, w23, w31, (float*)d_out, npts);
    (void)n_in; (void)out_size;
}

// round 8
// speedup vs baseline: 4.9968x; 4.2305x over previous
#include <cuda_runtime.h>
#include <cuda_fp16.h>
#include <math.h>
#include <stdint.h>

// ===========================================================================
// FFNerf fused inference via mma.sync.m16n8k16.f16 (split hi/lo fp16, 3 mma
// per product: lo*hi + hi*lo + hi*hi; fp32 accumulate).
//
// Per CTA: 64 points, 256 threads = 8 warps (4 M-warps x 2 N-warps).
// Activations: smem, PRE-SPLIT half hi/lo, [64][K] row-major pitch 136
//   (bank-conflict-free LDS.32 fragment loads). Epilogue writes splits.
// Weights: prep kernel packs per-lane mma B-fragments into uint4 images
//   {bh0,bh1,bl0,bl1} indexed [ks][ntile][lane] -> one LDG.128 per
//   (k-step, n-tile), coalesced, L2-resident.
// sigma folded into L8 GEMM (w23 padded to N=144; col 128 = sigma).
// Color head 64->3 via mma (N padded to 8), sigmoid at write.
// Output: color (3N) then sigma (N).
// ===========================================================================

constexpr int MPTS     = 64;
constexpr int NTHREADS = 256;

constexpr int AP = 136;   // A pitch in halves ((136*2/4)%32==4 -> conflict-free)
constexpr int XP = 72;    // X pitch in halves

// smem half-index offsets
constexpr int S_AHI = 0;
constexpr int S_ALO = S_AHI + MPTS * AP;      // 8704
constexpr int S_XHI = S_ALO + MPTS * AP;      // 17408
constexpr int S_XLO = S_XHI + MPTS * XP;      // 22016
constexpr int SMEM_HALVES = S_XLO + MPTS * XP;  // 26624
constexpr int SMEM_BYTES  = SMEM_HALVES * 2;    // 53248

// weight image section offsets (uint4 units); size = NKS*NTG*32
constexpr int O_L0   = 0;            // NKS4  NTG16 -> 2048
constexpr int O_L1   = 2048;         // NKS8  NTG16 -> 4096
constexpr int O_L2   = 6144;
constexpr int O_L3   = 10240;
constexpr int O_L4   = 14336;
constexpr int O_L5A  = 18432;        // 4096
constexpr int O_L5X  = 22528;        // NKS4  NTG16 -> 2048
constexpr int O_L6   = 24576;
constexpr int O_L7   = 28672;
constexpr int O_L8   = 32768;        // NKS8  NTG18 -> 4608
constexpr int O_L9A  = 37376;        // NKS8  NTG8  -> 2048
constexpr int O_L9X  = 39424;        // NKS2  NTG8  -> 512
constexpr int O_HEAD = 39936;        // NKS4  NTG1  -> 128
constexpr int IMG_TOTAL = 40064;     // uint4 -> 641 KB

__device__ uint4 g_img[IMG_TOTAL];

// ---------------- prep: pack per-lane B fragments --------------------------
__device__ __forceinline__ uint32_t pack_h2(__half a, __half b) {
    __half2 v = __halves2half2(a, b);
    return *reinterpret_cast<uint32_t*>(&v);
}

__global__ void prep_pack_kernel(const float* __restrict__ src, int pitch,
                                 int kReal, int row0, int nMax,
                                 int NKS, int NTG, int dstOff)
{
    int idx = blockIdx.x * blockDim.x + threadIdx.x;
    int total = NKS * NTG * 32;
    if (idx >= total) return;
    int lane = idx & 31;
    int rest = idx >> 5;
    int ntg  = rest % NTG;
    int ks   = rest / NTG;
    int g = lane >> 2, t = lane & 3;
    int n = ntg * 8 + g;
    int kk[4] = { ks*16 + 2*t, ks*16 + 2*t + 1, ks*16 + 2*t + 8, ks*16 + 2*t + 9 };
    float w[4];
    __half h[4], l[4];
    #pragma unroll
    for (int j = 0; j < 4; ++j) {
        w[j] = (kk[j] < kReal && n < nMax) ? src[(row0 + kk[j]) * pitch + n] : 0.f;
        h[j] = __float2half_rn(w[j]);
        l[j] = __float2half_rn(w[j] - __half2float(h[j]));
    }
    g_img[dstOff + idx] = make_uint4(pack_h2(h[0], h[1]), pack_h2(h[2], h[3]),
                                     pack_h2(l[0], l[1]), pack_h2(l[2], l[3]));
}

// ---------------- mma ------------------------------------------------------
__device__ __forceinline__ void mma16816(float* c, const uint32_t* a,
                                         uint32_t b0, uint32_t b1) {
    asm volatile(
        "mma.sync.aligned.m16n8k16.row.col.f32.f16.f16.f32 "
        "{%0,%1,%2,%3}, {%4,%5,%6,%7}, {%8,%9}, {%0,%1,%2,%3};"
        : "+f"(c[0]), "+f"(c[1]), "+f"(c[2]), "+f"(c[3])
        : "r"(a[0]), "r"(a[1]), "r"(a[2]), "r"(a[3]), "r"(b0), "r"(b1));
}

// Accumulate NKS k-steps x NT n-tiles from split-half activations + image.
template <int NKS, int NT>
__device__ __forceinline__ void mma_loop(
    float (*c)[4], const __half* Hi, const __half* Lo, int P,
    const uint4* __restrict__ img, int NTG, int nt0, int m0, int lane)
{
    const int g = lane >> 2, t = lane & 3;
    const int r0 = (m0 + g) * P;
    const int r1 = r0 + 8 * P;
    #pragma unroll
    for (int ks = 0; ks < NKS; ++ks) {
        const int cb = ks * 16 + 2 * t;
        uint32_t ah[4], al[4];
        ah[0] = *(const uint32_t*)(Hi + r0 + cb);
        ah[1] = *(const uint32_t*)(Hi + r1 + cb);
        ah[2] = *(const uint32_t*)(Hi + r0 + cb + 8);
        ah[3] = *(const uint32_t*)(Hi + r1 + cb + 8);
        al[0] = *(const uint32_t*)(Lo + r0 + cb);
        al[1] = *(const uint32_t*)(Lo + r1 + cb);
        al[2] = *(const uint32_t*)(Lo + r0 + cb + 8);
        al[3] = *(const uint32_t*)(Lo + r1 + cb + 8);
        const uint4* ib = img + (ks * NTG + nt0) * 32 + lane;
        #pragma unroll
        for (int n0 = 0; n0 < NT; n0 += 4) {
            uint4 b[4];
            #pragma unroll
            for (int j = 0; j < 4; ++j)
                if (n0 + j < NT) b[j] = __ldg(ib + (n0 + j) * 32);
            #pragma unroll
            for (int j = 0; j < 4; ++j)
                if (n0 + j < NT) mma16816(c[n0 + j], al, b[j].x, b[j].y);
            #pragma unroll
            for (int j = 0; j < 4; ++j)
                if (n0 + j < NT) mma16816(c[n0 + j], ah, b[j].z, b[j].w);
            #pragma unroll
            for (int j = 0; j < 4; ++j)
                if (n0 + j < NT) mma16816(c[n0 + j], ah, b[j].x, b[j].y);
        }
    }
}

// Split-store a pair of values (cols col, col+1) at half-index idx.
__device__ __forceinline__ void store_split(__half* Hi, __half* Lo, int idx,
                                            float v0, float v1) {
    __half h0 = __float2half_rn(v0);
    __half h1 = __float2half_rn(v1);
    __half l0 = __float2half_rn(v0 - __half2float(h0));
    __half l1 = __float2half_rn(v1 - __half2float(h1));
    *reinterpret_cast<__half2*>(Hi + idx) = __halves2half2(h0, h1);
    *reinterpret_cast<__half2*>(Lo + idx) = __halves2half2(l0, l1);
}

// Write NT tiles of C into split activation buffer (pitch P, relu optional).
template <int NT, bool RELU>
__device__ __forceinline__ void write_act(
    float (*c)[4], __half* Hi, __half* Lo, int P, int nt0, int m0, int lane)
{
    const int g = lane >> 2, t = lane & 3;
    const int r0 = (m0 + g) * P;
    const int r1 = r0 + 8 * P;
    #pragma unroll
    for (int nt = 0; nt < NT; ++nt) {
        int col = (nt0 + nt) * 8 + 2 * t;
        float v0 = c[nt][0], v1 = c[nt][1], v2 = c[nt][2], v3 = c[nt][3];
        if (RELU) {
            v0 = fmaxf(v0, 0.f); v1 = fmaxf(v1, 0.f);
            v2 = fmaxf(v2, 0.f); v3 = fmaxf(v3, 0.f);
        }
        store_split(Hi, Lo, r0 + col, v0, v1);
        store_split(Hi, Lo, r1 + col, v2, v3);
    }
}

__device__ __forceinline__ void put_x(__half* XHi, __half* XLo, int row,
                                      int col, float v) {
    int idx = row * XP + col;
    __half h = __float2half_rn(v);
    XHi[idx] = h;
    XLo[idx] = __float2half_rn(v - __half2float(h));
}

// ---------------- main kernel ----------------------------------------------
__global__ void __launch_bounds__(NTHREADS)
ffnerf_hmma_kernel(const float* __restrict__ pos,
                   const float* __restrict__ dirs,
                   float* __restrict__ out, int npts)
{
    extern __shared__ __half smh[];
    __half* AHi = smh + S_AHI;
    __half* ALo = smh + S_ALO;
    __half* XHi = smh + S_XHI;
    __half* XLo = smh + S_XLO;

    const int tid  = threadIdx.x;
    const int lane = tid & 31;
    const int warp = tid >> 5;
    const int g    = lane >> 2;
    const int t    = lane & 3;
    const int wm   = warp & 3;
    const int wn   = warp >> 2;
    const int m0   = wm * 16;
    const int g0   = blockIdx.x * MPTS;

    // --- posenc x_emb (63 features, col 63 zero) ---------------------------
    if (tid < MPTS) {
        int gp = g0 + tid;
        float p0 = pos[gp*3+0], p1 = pos[gp*3+1], p2 = pos[gp*3+2];
        put_x(XHi, XLo, tid, 0, p0);
        put_x(XHi, XLo, tid, 1, p1);
        put_x(XHi, XLo, tid, 2, p2);
        #pragma unroll
        for (int j = 0; j < 10; ++j) {
            float f = (float)(1 << j);
            float s0, c0, s1, c1, s2, c2;
            sincosf(f * p0, &s0, &c0);
            sincosf(f * p1, &s1, &c1);
            sincosf(f * p2, &s2, &c2);
            put_x(XHi, XLo, tid, 3 + 6*j + 0, s0);
            put_x(XHi, XLo, tid, 3 + 6*j + 1, s1);
            put_x(XHi, XLo, tid, 3 + 6*j + 2, s2);
            put_x(XHi, XLo, tid, 3 + 6*j + 3, c0);
            put_x(XHi, XLo, tid, 3 + 6*j + 4, c1);
            put_x(XHi, XLo, tid, 3 + 6*j + 5, c2);
        }
        put_x(XHi, XLo, tid, 63, 0.f);
    }
    __syncthreads();

    // --- L0: x_emb(64) -> 128, relu ---------------------------------------
    {
        float c[8][4];
        #pragma unroll
        for (int i = 0; i < 8; ++i)
            #pragma unroll
            for (int j = 0; j < 4; ++j) c[i][j] = 0.f;
        mma_loop<4, 8>(c, XHi, XLo, XP, g_img + O_L0, 16, wn * 8, m0, lane);
        __syncthreads();
        write_act<8, true>(c, AHi, ALo, AP, wn * 8, m0, lane);
        __syncthreads();
    }

    // --- L1..L4, L6, L7: 128 -> 128, relu (in-place A) --------------------
    const int mids[6] = { O_L1, O_L2, O_L3, O_L4, -1, -1 };
    #pragma unroll
    for (int li = 0; li < 4; ++li) {
        float c[8][4];
        #pragma unroll
        for (int i = 0; i < 8; ++i)
            #pragma unroll
            for (int j = 0; j < 4; ++j) c[i][j] = 0.f;
        mma_loop<8, 8>(c, AHi, ALo, AP, g_img + mids[li], 16, wn * 8, m0, lane);
        __syncthreads();
        write_act<8, true>(c, AHi, ALo, AP, wn * 8, m0, lane);
        __syncthreads();
    }

    // --- L5: [h | x_emb](192) -> 128, relu; then d_emb into X -------------
    {
        float c[8][4];
        #pragma unroll
        for (int i = 0; i < 8; ++i)
            #pragma unroll
            for (int j = 0; j < 4; ++j) c[i][j] = 0.f;
        mma_loop<8, 8>(c, AHi, ALo, AP, g_img + O_L5A, 16, wn * 8, m0, lane);
        mma_loop<4, 8>(c, XHi, XLo, XP, g_img + O_L5X, 16, wn * 8, m0, lane);
        __syncthreads();
        write_act<8, true>(c, AHi, ALo, AP, wn * 8, m0, lane);
        // d_emb posenc (27 features, cols 27..31 zero) — X fully consumed
        if (tid < MPTS) {
            int gp = g0 + tid;
            float d0 = dirs[gp*3+0], d1 = dirs[gp*3+1], d2 = dirs[gp*3+2];
            put_x(XHi, XLo, tid, 0, d0);
            put_x(XHi, XLo, tid, 1, d1);
            put_x(XHi, XLo, tid, 2, d2);
            #pragma unroll
            for (int j = 0; j < 4; ++j) {
                float f = (float)(1 << j);
                float s0, c0, s1, c1, s2, c2;
                sincosf(f * d0, &s0, &c0);
                sincosf(f * d1, &s1, &c1);
                sincosf(f * d2, &s2, &c2);
                put_x(XHi, XLo, tid, 3 + 6*j + 0, s0);
                put_x(XHi, XLo, tid, 3 + 6*j + 1, s1);
                put_x(XHi, XLo, tid, 3 + 6*j + 2, s2);
                put_x(XHi, XLo, tid, 3 + 6*j + 3, c0);
                put_x(XHi, XLo, tid, 3 + 6*j + 4, c1);
                put_x(XHi, XLo, tid, 3 + 6*j + 5, c2);
            }
            #pragma unroll
            for (int z = 27; z < 32; ++z) put_x(XHi, XLo, tid, z, 0.f);
        }
        __syncthreads();
    }

    // --- L6, L7 -----------------------------------------------------------
    #pragma unroll
    for (int li = 0; li < 2; ++li) {
        float c[8][4];
        #pragma unroll
        for (int i = 0; i < 8; ++i)
            #pragma unroll
            for (int j = 0; j < 4; ++j) c[i][j] = 0.f;
        mma_loop<8, 8>(c, AHi, ALo, AP, g_img + (li == 0 ? O_L6 : O_L7), 16,
                       wn * 8, m0, lane);
        __syncthreads();
        write_act<8, true>(c, AHi, ALo, AP, wn * 8, m0, lane);
        __syncthreads();
    }

    // --- L8: 128 -> 144-pad (feat cols 0..127 linear, col 128 = sigma) ----
    {
        float c[9][4];
        #pragma unroll
        for (int i = 0; i < 9; ++i)
            #pragma unroll
            for (int j = 0; j < 4; ++j) c[i][j] = 0.f;
        mma_loop<8, 9>(c, AHi, ALo, AP, g_img + O_L8, 18, wn * 9, m0, lane);
        __syncthreads();
        const int r0 = (m0 + g) * AP;
        const int r1 = r0 + 8 * AP;
        float* sigma = out + (size_t)3 * npts + g0;
        #pragma unroll
        for (int nt = 0; nt < 9; ++nt) {
            int colb = (wn * 9 + nt) * 8;
            if (colb < 128) {                       // feat, linear
                int col = colb + 2 * t;
                store_split(AHi, ALo, r0 + col, c[nt][0], c[nt][1]);
                store_split(AHi, ALo, r1 + col, c[nt][2], c[nt][3]);
            } else if (colb == 128 && t == 0) {     // sigma column
                sigma[m0 + g]     = fmaxf(c[nt][0], 0.f);
                sigma[m0 + g + 8] = fmaxf(c[nt][2], 0.f);
            }
        }
        __syncthreads();
    }

    // --- L9: [feat | d_emb] -> 64, relu -----------------------------------
    {
        float c[4][4];
        #pragma unroll
        for (int i = 0; i < 4; ++i)
            #pragma unroll
            for (int j = 0; j < 4; ++j) c[i][j] = 0.f;
        mma_loop<8, 4>(c, AHi, ALo, AP, g_img + O_L9A, 8, wn * 4, m0, lane);
        mma_loop<2, 4>(c, XHi, XLo, XP, g_img + O_L9X, 8, wn * 4, m0, lane);
        __syncthreads();
        write_act<4, true>(c, AHi, ALo, AP, wn * 4, m0, lane);
        __syncthreads();
    }

    // --- head: 64 -> 3 (pad 8), sigmoid -> color --------------------------
    if (wn == 0) {
        float c[1][4];
        c[0][0] = c[0][1] = c[0][2] = c[0][3] = 0.f;
        mma_loop<4, 1>(c, AHi, ALo, AP, g_img + O_HEAD, 1, 0, m0, lane);
        int row0 = g0 + m0 + g;
        int row1 = row0 + 8;
        if (t == 0) {
            out[row0*3 + 0] = 1.f / (1.f + expf(-c[0][0]));
            out[row0*3 + 1] = 1.f / (1.f + expf(-c[0][1]));
            out[row1*3 + 0] = 1.f / (1.f + expf(-c[0][2]));
            out[row1*3 + 1] = 1.f / (1.f + expf(-c[0][3]));
        } else if (t == 1) {
            out[row0*3 + 2] = 1.f / (1.f + expf(-c[0][0]));
            out[row1*3 + 2] = 1.f / (1.f + expf(-c[0][2]));
        }
    }
}

// ---------------- launch ----------------------------------------------------
extern "C" void kernel_launch(void* const* d_in, const int* in_sizes, int n_in,
                              void* d_out, int out_size)
{
    const float* pos  = (const float*)d_in[0];
    const float* dirs = (const float*)d_in[1];
    const float* w10  = (const float*)d_in[2];
    const float* w11  = (const float*)d_in[3];
    const float* w12  = (const float*)d_in[4];
    const float* w13  = (const float*)d_in[5];
    const float* w14  = (const float*)d_in[6];
    const float* w20  = (const float*)d_in[7];
    const float* w21  = (const float*)d_in[8];
    const float* w22  = (const float*)d_in[9];
    const float* w23  = (const float*)d_in[10];
    const float* w30  = (const float*)d_in[11];
    const float* w31  = (const float*)d_in[12];

    int npts = in_sizes[0] / 3;
    int nblocks = npts / MPTS;

    auto prep = [](const float* src, int pitch, int kReal, int row0, int nMax,
                   int NKS, int NTG, int dstOff) {
        int n = NKS * NTG * 32;
        prep_pack_kernel<<<(n + 255) / 256, 256>>>(src, pitch, kReal, row0,
                                                   nMax, NKS, NTG, dstOff);
    };
    prep(w10, 128,  63,   0, 128, 4, 16, O_L0);
    prep(w11, 128, 128,   0, 128, 8, 16, O_L1);
    prep(w12, 128, 128,   0, 128, 8, 16, O_L2);
    prep(w13, 128, 128,   0, 128, 8, 16, O_L3);
    prep(w14, 128, 128,   0, 128, 8, 16, O_L4);
    prep(w20, 128, 128,   0, 128, 8, 16, O_L5A);
    prep(w20, 128,  63, 128, 128, 4, 16, O_L5X);
    prep(w21, 128, 128,   0, 128, 8, 16, O_L6);
    prep(w22, 128, 128,   0, 128, 8, 16, O_L7);
    prep(w23, 129, 128,   0, 129, 8, 18, O_L8);
    prep(w30,  64, 128,   0,  64, 8,  8, O_L9A);
    prep(w30,  64,  27, 128,  64, 2,  8, O_L9X);
    prep(w31,   3,  64,   0,   3, 4,  1, O_HEAD);

    cudaFuncSetAttribute(ffnerf_hmma_kernel,
                         cudaFuncAttributeMaxDynamicSharedMemorySize, SMEM_BYTES);
    ffnerf_hmma_kernel<<<nblocks, NTHREADS, SMEM_BYTES>>>(
        pos, dirs, (float*)d_out, npts);
    (void)n_in; (void)out_size;
}